// round 16
// baseline (speedup 1.0000x reference)
#include <cuda_runtime.h>
#include <cuda_fp16.h>
#include <cstdint>
#include <cstddef>

// Problem constants
#define Bb   8
#define Ll   4160
#define Dd   1024
#define Hh   16
#define NBb  64
#define BLb  64
#define NSs  64
#define NTt  4096   // NB*BL
#define Mtot (Bb*Ll)      // 33280

// Scratch (device globals: allocation-free)
__device__ float g_Q [(size_t)Mtot*Dd];
__device__ float g_K [(size_t)Mtot*Dd];
__device__ float g_V [(size_t)Mtot*Dd];
__device__ float g_K2[(size_t)Mtot*Dd];
__device__ float g_V2[(size_t)Mtot*Dd];
__device__ float g_QS[(size_t)Bb*NSs*Dd];
__device__ float g_S [(size_t)Bb*NSs*Dd];
__device__ __half g_Wc[5][(size_t)Dd*Dd];
__device__ float g_Wcomb[2][(size_t)Dd*Dd];
__device__ float g_bck[Dd];
__device__ float g_bcv[Dd];
__device__ float g_zero[Dd];   // zero-initialized, never written

// ===========================================================================
// helpers
// ===========================================================================
__device__ __forceinline__ uint32_t smem_u32(const void* p) {
    uint32_t a;
    asm("{ .reg .u64 t; cvta.to.shared.u64 t, %1; cvt.u32.u64 %0, t; }"
        : "=r"(a) : "l"(p));
    return a;
}
__device__ __forceinline__ void ldsm4(uint32_t* r, uint32_t addr) {
    asm volatile("ldmatrix.sync.aligned.m8n8.x4.shared.b16 {%0,%1,%2,%3}, [%4];"
                 : "=r"(r[0]), "=r"(r[1]), "=r"(r[2]), "=r"(r[3]) : "r"(addr));
}
__device__ __forceinline__ void mma16816h(float* d, const uint32_t* a,
                                          uint32_t b0, uint32_t b1) {
    asm volatile("mma.sync.aligned.m16n8k16.row.col.f32.f16.f16.f32 "
                 "{%0,%1,%2,%3}, {%4,%5,%6,%7}, {%8,%9}, {%0,%1,%2,%3};"
                 : "+f"(d[0]), "+f"(d[1]), "+f"(d[2]), "+f"(d[3])
                 : "r"(a[0]), "r"(a[1]), "r"(a[2]), "r"(a[3]), "r"(b0), "r"(b1));
}
__device__ __forceinline__ void cpasync16(uint32_t d, const void* g) {
    asm volatile("cp.async.cg.shared.global [%0], [%1], 16;" :: "r"(d), "l"(g));
}
__device__ __forceinline__ uint32_t packh2(__half a, __half b) {
    __half2 p = __halves2half2(a, b);
    return *(uint32_t*)&p;
}

// ===========================================================================
// Convert X fp32 -> Y fp16 (contiguous, used for weights only now).
// ===========================================================================
__global__ void __launch_bounds__(256)
conv_hi(const float* __restrict__ X, __half* __restrict__ Y, int n4)
{
    int i = blockIdx.x * blockDim.x + threadIdx.x;
    if (i >= n4) return;
    float4 v = ((const float4*)X)[i];
    uint2 hv = make_uint2(packh2(__float2half_rn(v.x), __float2half_rn(v.y)),
                          packh2(__float2half_rn(v.z), __float2half_rn(v.w)));
    *(uint2*)(Y + ((size_t)i << 2)) = hv;
}

// ===========================================================================
// bias combine: out[i] = dot(W2 row i, b1) + b2[i].  grid = 1024 blocks.
// ===========================================================================
__global__ void __launch_bounds__(256)
bias_comb(const float* __restrict__ W2, const float* __restrict__ b1,
          const float* __restrict__ b2, float* __restrict__ out)
{
    __shared__ float red[256];
    int i = blockIdx.x;
    float s = 0.0f;
    for (int k = threadIdx.x; k < Dd; k += 256)
        s += W2[(size_t)i * Dd + k] * b1[k];
    red[threadIdx.x] = s;
    __syncthreads();
    for (int st = 128; st > 0; st >>= 1) {
        if (threadIdx.x < st) red[threadIdx.x] += red[threadIdx.x + st];
        __syncthreads();
    }
    if (threadIdx.x == 0) out[i] = red[0] + b2[i];
}

// ===========================================================================
// fp16 TN GEMM with fused A conversion:
//   C[M,1024] = fp16(A_fp32[M,1024]) @ W_fp16[1024,1024]^T + bias
// A loaded as fp32 (LDG), converted in registers, STS'ed into swizzled smem.
// W streamed via cp.async. Block 128x128, warp 32x64, k-chunk 64, 2 stages.
// ===========================================================================
#define GB_SMEM (2*32768)

__global__ void __launch_bounds__(256)
gemm_fp16(const float* __restrict__ A, const __half* __restrict__ W,
          const float* __restrict__ bias, float* __restrict__ C)
{
    extern __shared__ char gsm[];
    const uint32_t sb = smem_u32(gsm);
    const int t = threadIdx.x;
    const int m0 = blockIdx.y * 128;
    const int n0 = blockIdx.x * 128;

    const int l = t & 31, wid = t >> 5;
    const int wm = (wid & 3) * 32;
    const int wn = (wid >> 2) * 64;
    const int lr = (l & 7) + ((l >> 3) & 1) * 8;
    const int khalf = l >> 4;

    uint32_t aoff[2], asw[2];
    #pragma unroll
    for (int i = 0; i < 2; i++) {
        int row = wm + i * 16 + lr;
        aoff[i] = row * 128;
        asw[i]  = row & 7;
    }
    uint32_t boff[4], bsw[4];
    #pragma unroll
    for (int pr = 0; pr < 4; pr++) {
        int row = wn + pr * 16 + lr;
        boff[pr] = row * 128;
        bsw[pr]  = row & 7;
    }

    float acc[2][8][4];
    #pragma unroll
    for (int i = 0; i < 2; i++)
        #pragma unroll
        for (int j = 0; j < 8; j++)
            #pragma unroll
            for (int z = 0; z < 4; z++) acc[i][j][z] = 0.0f;

    const int NCH = 16;
    // per-thread A units: e = it*256 + t, row = e>>3, seg = e&7 (16B fp16 units)
    uint32_t ah[16];

    auto ldg_conv = [&](int s) {
        const float* Ag = A + (size_t)m0 * 1024 + s * 64;
        #pragma unroll
        for (int it = 0; it < 4; it++) {
            int e = it * 256 + t;
            int row = e >> 3, seg = e & 7;
            const float* src = Ag + (size_t)row * 1024 + seg * 8;
            float4 v0 = *(const float4*)(src);
            float4 v1 = *(const float4*)(src + 4);
            ah[it*4+0] = packh2(__float2half_rn(v0.x), __float2half_rn(v0.y));
            ah[it*4+1] = packh2(__float2half_rn(v0.z), __float2half_rn(v0.w));
            ah[it*4+2] = packh2(__float2half_rn(v1.x), __float2half_rn(v1.y));
            ah[it*4+3] = packh2(__float2half_rn(v1.z), __float2half_rn(v1.w));
        }
    };
    auto sts_a = [&](int p) {
        char* sa = gsm + p * 32768;
        #pragma unroll
        for (int it = 0; it < 4; it++) {
            int e = it * 256 + t;
            int row = e >> 3, seg = e & 7;
            uint32_t sw = (uint32_t)((seg ^ (row & 7)) << 4);
            *(uint4*)(sa + row * 128 + sw) =
                make_uint4(ah[it*4], ah[it*4+1], ah[it*4+2], ah[it*4+3]);
        }
    };
    auto load_w = [&](int s) {
        int p = s & 1;
        uint32_t sbb = sb + p * 32768 + 16384;
        const __half* Wg = W + (size_t)n0 * 1024 + s * 64;
        #pragma unroll
        for (int it = 0; it < 4; it++) {
            int e = it * 256 + t;
            int row = e >> 3, seg = e & 7;
            uint32_t sw = (uint32_t)((seg ^ (row & 7)) << 4);
            cpasync16(sbb + row * 128 + sw, Wg + (size_t)row * 1024 + seg * 8);
        }
        asm volatile("cp.async.commit_group;");
    };

    ldg_conv(0);
    load_w(0);

    for (int s = 0; s < NCH; s++) {
        const int p = s & 1;
        sts_a(p);                       // A(s) -> buf p (regs from prev iter)
        if (s + 1 < NCH) {
            ldg_conv(s + 1);            // prefetch A(s+1) into regs
            load_w(s + 1);
            asm volatile("cp.async.wait_group 1;");
        } else {
            asm volatile("cp.async.wait_group 0;");
        }
        __syncthreads();

        const uint32_t sa  = sb + p * 32768;
        const uint32_t sbb = sa + 16384;
        #pragma unroll
        for (int k2 = 0; k2 < 4; k2++) {
            uint32_t areg[2][4];
            #pragma unroll
            for (int i = 0; i < 2; i++)
                ldsm4(areg[i], sa + aoff[i] + ((((uint32_t)(k2*2 + khalf)) ^ asw[i]) << 4));
            uint32_t breg[4][4];
            #pragma unroll
            for (int pr = 0; pr < 4; pr++)
                ldsm4(breg[pr], sbb + boff[pr] + ((((uint32_t)(k2*2 + khalf)) ^ bsw[pr]) << 4));
            #pragma unroll
            for (int i = 0; i < 2; i++)
                #pragma unroll
                for (int j = 0; j < 8; j++)
                    mma16816h(acc[i][j], areg[i],
                              breg[j >> 1][j & 1], breg[j >> 1][2 + (j & 1)]);
        }
        __syncthreads();
    }

    const int r = l >> 2, q = l & 3;
    #pragma unroll
    for (int i = 0; i < 2; i++) {
        int row = m0 + wm + i * 16 + r;
        #pragma unroll
        for (int j = 0; j < 8; j++) {
            int col = n0 + wn + j * 8 + q * 2;
            float b0 = bias[col], b1 = bias[col + 1];
            *(float2*)(C + (size_t)row * 1024 + col) =
                make_float2(acc[i][j][0] + b0, acc[i][j][1] + b1);
            *(float2*)(C + (size_t)(row + 8) * 1024 + col) =
                make_float2(acc[i][j][2] + b0, acc[i][j][3] + b1);
        }
    }
}

// ===========================================================================
// SIMT SGEMM, 128x128 tiles: C = A @ op(W) + bias
// modeW: 0 -> W [N,K] row-major (A@W^T);  1 -> W [K,N] row-major (A@W)
// modeA: 1 = gather rows via sidx; modeC: 1 = scatter rows to b*L+NT+q
// ===========================================================================
__global__ void __launch_bounds__(256)
sgemm_bias(const float* __restrict__ A, const float* __restrict__ W,
           const float* __restrict__ bias, float* __restrict__ C,
           int M, int N, int K,
           int modeA, const int* __restrict__ sidx, int modeC, int modeW)
{
    __shared__ float As[8][128];
    __shared__ float Bs[8][128];
    const int t    = threadIdx.x;
    const int row0 = blockIdx.y * 128;
    const int col0 = blockIdx.x * 128;
    const int a_r = t >> 1;
    const int a_c = (t & 1) << 2;
    int arow = row0 + a_r;
    size_t a_base;
    if (modeA == 1) {
        int bi = arow >> 6, qq = arow & 63;
        a_base = ((size_t)bi * Ll + (size_t)sidx[qq]) * (size_t)K;
    } else {
        a_base = (size_t)arow * (size_t)K;
    }
    const size_t w_base = (size_t)(col0 + a_r) * (size_t)K;
    const int kk2 = t >> 5;
    const int n4  = (t & 31) << 2;
    const int tr = (t >> 4) << 3;
    const int tc = (t & 15) << 3;
    float acc[8][8];
    #pragma unroll
    for (int i = 0; i < 8; i++)
        #pragma unroll
        for (int j = 0; j < 8; j++) acc[i][j] = 0.0f;
    for (int k0 = 0; k0 < K; k0 += 8) {
        float4 av = *(const float4*)(A + a_base + k0 + a_c);
        As[a_c+0][a_r] = av.x; As[a_c+1][a_r] = av.y;
        As[a_c+2][a_r] = av.z; As[a_c+3][a_r] = av.w;
        if (modeW == 0) {
            float4 wv = *(const float4*)(W + w_base + k0 + a_c);
            Bs[a_c+0][a_r] = wv.x; Bs[a_c+1][a_r] = wv.y;
            Bs[a_c+2][a_r] = wv.z; Bs[a_c+3][a_r] = wv.w;
        } else {
            float4 wv = *(const float4*)(W + (size_t)(k0 + kk2) * N + col0 + n4);
            *(float4*)&Bs[kk2][n4] = wv;
        }
        __syncthreads();
        #pragma unroll
        for (int k = 0; k < 8; k++) {
            float ra[8], rb[8];
            *(float4*)&ra[0] = *(const float4*)&As[k][tr];
            *(float4*)&ra[4] = *(const float4*)&As[k][tr+4];
            *(float4*)&rb[0] = *(const float4*)&Bs[k][tc];
            *(float4*)&rb[4] = *(const float4*)&Bs[k][tc+4];
            #pragma unroll
            for (int i = 0; i < 8; i++)
                #pragma unroll
                for (int j = 0; j < 8; j++)
                    acc[i][j] = fmaf(ra[i], rb[j], acc[i][j]);
        }
        __syncthreads();
    }
    #pragma unroll
    for (int i = 0; i < 8; i++) {
        int r = row0 + tr + i;
        int orow = (modeC == 1) ? ((r >> 6) * Ll + NTt + (r & 63)) : r;
        float* cp = C + (size_t)orow * (size_t)N + col0 + tc;
        #pragma unroll
        for (int j = 0; j < 8; j++)
            cp[j] = acc[i][j] + bias[col0 + tc + j];
    }
}

// ===========================================================================
// Temporal block attention — tensor-core version.
// ===========================================================================
#define TA_SMEM (62464 + 33792 + 512)

__global__ void __launch_bounds__(256)
temporal_attn(const float* __restrict__ Q, const float* __restrict__ K,
              const float* __restrict__ V,
              const int* __restrict__ tidx, const int* __restrict__ sidx,
              const float* __restrict__ tpm, const float* __restrict__ spm,
              float* __restrict__ out)
{
    const int h = blockIdx.x, nb = blockIdx.y, b = blockIdx.z;
    const int t = threadIdx.x;
    extern __shared__ char smc[];
    __half* sqh  = (__half*)smc;        // 64 x 72
    __half* skh  = sqh + 4608;          // 128 x 72
    __half* svT  = skh + 9216;          // 64 x 136
    __half* sp16 = svT + 8704;          // 64 x 136
    float*  sp   = (float*)(smc + 62464);
    float*  sbias= sp + 64*132;

    const uint32_t sqh_u  = smem_u32(sqh);
    const uint32_t skh_u  = smem_u32(skh);
    const uint32_t svT_u  = smem_u32(svT);
    const uint32_t sp16_u = smem_u32(sp16);

    if (t < 128) {
        float mk = (t < 64) ? tpm[((b*NBb)+nb)*BLb + t] : spm[b*NSs + (t-64)];
        sbias[t] = (mk == 1.0f) ? 0.0f : -1e30f;
    }
    for (int e = t; e < 64*64; e += 256) {
        int r = e >> 6, k = e & 63;
        int grow = tidx[nb*64 + r];
        sqh[r*72 + k] = __float2half_rn(Q[((size_t)b*Ll + grow)*Dd + h*64 + k]);
    }
    for (int e = t; e < 128*64; e += 256) {
        int r = e >> 6, k = e & 63;
        int grow = (r < 64) ? tidx[nb*64 + r] : sidx[r - 64];
        skh[r*72 + k] = __float2half_rn(K[((size_t)b*Ll + grow)*Dd + h*64 + k]);
    }
    for (int e = t; e < 128*64; e += 256) {
        int j = e >> 6, d = e & 63;
        int grow = (j < 64) ? tidx[nb*64 + j] : sidx[j - 64];
        svT[d*136 + j] = __float2half_rn(V[((size_t)b*Ll + grow)*Dd + h*64 + d]);
    }
    __syncthreads();

    const int l = t & 31, wid = t >> 5;
    const int lr = (l & 7) + ((l >> 3) & 1) * 8;
    const int khalf = l >> 4;
    const int rr = l >> 2, qq = l & 3;

    // logits = Q @ K^T * scale + bias
    {
        const int wm = (wid & 1) * 32;
        const int wn = (wid >> 1) * 32;
        float acc[2][4][4];
        #pragma unroll
        for (int i = 0; i < 2; i++)
            #pragma unroll
            for (int j = 0; j < 4; j++)
                #pragma unroll
                for (int z = 0; z < 4; z++) acc[i][j][z] = 0.0f;
        #pragma unroll
        for (int k2 = 0; k2 < 4; k2++) {
            const uint32_t kc = (uint32_t)(k2*2 + khalf);
            uint32_t areg[2][4], breg[2][4];
            #pragma unroll
            for (int i = 0; i < 2; i++)
                ldsm4(areg[i], sqh_u + (uint32_t)(wm + i*16 + lr)*144u + kc*16u);
            #pragma unroll
            for (int pr = 0; pr < 2; pr++)
                ldsm4(breg[pr], skh_u + (uint32_t)(wn + pr*16 + lr)*144u + kc*16u);
            #pragma unroll
            for (int i = 0; i < 2; i++)
                #pragma unroll
                for (int j = 0; j < 4; j++)
                    mma16816h(acc[i][j], areg[i],
                              breg[j >> 1][j & 1], breg[j >> 1][2 + (j & 1)]);
        }
        #pragma unroll
        for (int i = 0; i < 2; i++) {
            int row = wm + i*16 + rr;
            #pragma unroll
            for (int j = 0; j < 4; j++) {
                int col = wn + j*8 + qq*2;
                float b0 = sbias[col], b1 = sbias[col+1];
                sp[row*132 + col]       = acc[i][j][0]*0.125f + b0;
                sp[row*132 + col + 1]   = acc[i][j][1]*0.125f + b1;
                sp[(row+8)*132 + col]   = acc[i][j][2]*0.125f + b0;
                sp[(row+8)*132 + col+1] = acc[i][j][3]*0.125f + b1;
            }
        }
    }
    __syncthreads();

    // softmax -> fp16
    {
        const int row = t >> 2, lane4 = t & 3;
        float* rp = sp + row*132;
        __half* rp16 = sp16 + row*136;
        float mx = -1e30f;
        for (int c = lane4; c < 128; c += 4) mx = fmaxf(mx, rp[c]);
        mx = fmaxf(mx, __shfl_xor_sync(0xFFFFFFFFu, mx, 1));
        mx = fmaxf(mx, __shfl_xor_sync(0xFFFFFFFFu, mx, 2));
        float s = 0.0f;
        for (int c = lane4; c < 128; c += 4) { float p = __expf(rp[c]-mx); rp[c] = p; s += p; }
        s += __shfl_xor_sync(0xFFFFFFFFu, s, 1);
        s += __shfl_xor_sync(0xFFFFFFFFu, s, 2);
        float inv = 1.0f / s;
        for (int c = lane4; c < 128; c += 4) rp16[c] = __float2half_rn(rp[c]*inv);
    }
    __syncthreads();

    // out = P @ V
    {
        const int wm = (wid & 1) * 32;
        const int wn = (wid >> 1) * 16;
        float acc[2][2][4];
        #pragma unroll
        for (int i = 0; i < 2; i++)
            #pragma unroll
            for (int j = 0; j < 2; j++)
                #pragma unroll
                for (int z = 0; z < 4; z++) acc[i][j][z] = 0.0f;
        #pragma unroll
        for (int k2 = 0; k2 < 8; k2++) {
            const uint32_t kc = (uint32_t)(k2*2 + khalf);
            uint32_t areg[2][4], breg[4];
            #pragma unroll
            for (int i = 0; i < 2; i++)
                ldsm4(areg[i], sp16_u + (uint32_t)(wm + i*16 + lr)*272u + kc*16u);
            ldsm4(breg, svT_u + (uint32_t)(wn + lr)*272u + kc*16u);
            #pragma unroll
            for (int i = 0; i < 2; i++)
                #pragma unroll
                for (int j = 0; j < 2; j++)
                    mma16816h(acc[i][j], areg[i], breg[j], breg[2 + j]);
        }
        #pragma unroll
        for (int i = 0; i < 2; i++) {
            int row = wm + i*16 + rr;
            #pragma unroll
            for (int j = 0; j < 2; j++) {
                int col = h*64 + wn + j*8 + qq*2;
                *(float2*)(out + ((size_t)b*Ll + nb*64 + row)*Dd + col) =
                    make_float2(acc[i][j][0], acc[i][j][1]);
                *(float2*)(out + ((size_t)b*Ll + nb*64 + row + 8)*Dd + col) =
                    make_float2(acc[i][j][2], acc[i][j][3]);
            }
        }
    }
}

// ===========================================================================
// Static attention — tensor-core flash version.
// ===========================================================================
#define SA_SMEM 55296

__global__ void __launch_bounds__(256)
static_attn(const float* __restrict__ Qs, const float* __restrict__ K2,
            const float* __restrict__ V2,
            const int* __restrict__ tidx, const int* __restrict__ sidx,
            const float* __restrict__ tpm, const float* __restrict__ spm,
            float* __restrict__ S)
{
    const int h = blockIdx.x, b = blockIdx.y;
    const int t = threadIdx.x;
    extern __shared__ char smc[];
    __half* sqh  = (__half*)smc;            // 64 x 72
    __half* skh  = sqh + 4608;              // 64 x 72
    __half* svT  = skh + 4608;              // 64 x 72 (rows=d, cols=j)
    __half* sp16 = svT + 4608;              // 64 x 72
    float*  sp   = (float*)(smc + 36864);   // 64 x 68
    float*  mrow = (float*)(smc + 54272);
    float*  lrow = mrow + 64;
    float*  arow = lrow + 64;
    float*  sb2  = arow + 64;

    const uint32_t sqh_u  = smem_u32(sqh);
    const uint32_t skh_u  = smem_u32(skh);
    const uint32_t svT_u  = smem_u32(svT);
    const uint32_t sp16_u = smem_u32(sp16);

    for (int e = t; e < 4096; e += 256) {
        int r = e >> 6, k = e & 63;
        sqh[r*72 + k] = __float2half_rn(Qs[((size_t)b*64 + r)*Dd + h*64 + k]);
    }
    if (t < 64) { mrow[t] = -1e30f; lrow[t] = 0.0f; }

    const int l = t & 31, wid = t >> 5;
    const int lr = (l & 7) + ((l >> 3) & 1) * 8;
    const int khalf = l >> 4;
    const int rr = l >> 2, qq = l & 3;
    const int wm = (wid & 1) * 32;
    const int wn = (wid >> 1) * 16;

    float O[2][2][4];
    #pragma unroll
    for (int i = 0; i < 2; i++)
        #pragma unroll
        for (int j = 0; j < 2; j++)
            #pragma unroll
            for (int z = 0; z < 4; z++) O[i][j][z] = 0.0f;

    for (int jc = 0; jc < 65; jc++) {
        int base = jc * 64;
        __syncthreads();
        for (int e = t; e < 4096; e += 256) {
            int j = e >> 6, k = e & 63;
            int jj = base + j;
            int grow = (jj < NTt) ? tidx[jj] : sidx[jj - NTt];
            size_t gb = ((size_t)b*Ll + grow)*Dd + h*64 + k;
            skh[j*72 + k] = __float2half_rn(K2[gb]);
            svT[k*72 + j] = __float2half_rn(V2[gb]);
        }
        if (t < 64) {
            int jj = base + t;
            float mk = (jj < NTt) ? tpm[b*NTt + jj] : spm[b*NSs + (jj - NTt)];
            sb2[t] = (mk == 1.0f) ? 0.0f : -1e30f;
        }
        __syncthreads();

        // logits chunk: Q @ Kc^T
        {
            float acc[2][2][4];
            #pragma unroll
            for (int i = 0; i < 2; i++)
                #pragma unroll
                for (int j = 0; j < 2; j++)
                    #pragma unroll
                    for (int z = 0; z < 4; z++) acc[i][j][z] = 0.0f;
            #pragma unroll
            for (int k2 = 0; k2 < 4; k2++) {
                const uint32_t kc = (uint32_t)(k2*2 + khalf);
                uint32_t areg[2][4], breg[4];
                #pragma unroll
                for (int i = 0; i < 2; i++)
                    ldsm4(areg[i], sqh_u + (uint32_t)(wm + i*16 + lr)*144u + kc*16u);
                ldsm4(breg, skh_u + (uint32_t)(wn + lr)*144u + kc*16u);
                #pragma unroll
                for (int i = 0; i < 2; i++)
                    #pragma unroll
                    for (int j = 0; j < 2; j++)
                        mma16816h(acc[i][j], areg[i], breg[j], breg[2 + j]);
            }
            #pragma unroll
            for (int i = 0; i < 2; i++) {
                int row = wm + i*16 + rr;
                #pragma unroll
                for (int j = 0; j < 2; j++) {
                    int col = wn + j*8 + qq*2;
                    float b0 = sb2[col], b1 = sb2[col+1];
                    sp[row*68 + col]       = acc[i][j][0]*0.125f + b0;
                    sp[row*68 + col + 1]   = acc[i][j][1]*0.125f + b1;
                    sp[(row+8)*68 + col]   = acc[i][j][2]*0.125f + b0;
                    sp[(row+8)*68 + col+1] = acc[i][j][3]*0.125f + b1;
                }
            }
        }
        __syncthreads();

        // running softmax update, emit fp16 p
        {
            const int row = t >> 2, lane4 = t & 3;
            float* rp = sp + row*68;
            __half* rp16 = sp16 + row*72;
            float mold = mrow[row];
            float mx = mold;
            for (int c = lane4; c < 64; c += 4) mx = fmaxf(mx, rp[c]);
            mx = fmaxf(mx, __shfl_xor_sync(0xFFFFFFFFu, mx, 1));
            mx = fmaxf(mx, __shfl_xor_sync(0xFFFFFFFFu, mx, 2));
            float a = __expf(mold - mx);
            float ssum = 0.0f;
            for (int c = lane4; c < 64; c += 4) {
                float p = __expf(rp[c]-mx);
                rp16[c] = __float2half_rn(p);
                ssum += p;
            }
            ssum += __shfl_xor_sync(0xFFFFFFFFu, ssum, 1);
            ssum += __shfl_xor_sync(0xFFFFFFFFu, ssum, 2);
            if (lane4 == 0) {
                lrow[row] = lrow[row]*a + ssum;
                mrow[row] = mx;
                arow[row] = a;
            }
        }
        __syncthreads();

        // rescale O and accumulate P @ Vc
        {
            #pragma unroll
            for (int i = 0; i < 2; i++) {
                float a0 = arow[wm + i*16 + rr];
                float a1 = arow[wm + i*16 + rr + 8];
                #pragma unroll
                for (int j = 0; j < 2; j++) {
                    O[i][j][0] *= a0; O[i][j][1] *= a0;
                    O[i][j][2] *= a1; O[i][j][3] *= a1;
                }
            }
            #pragma unroll
            for (int k2 = 0; k2 < 4; k2++) {
                const uint32_t kc = (uint32_t)(k2*2 + khalf);
                uint32_t areg[2][4], breg[4];
                #pragma unroll
                for (int i = 0; i < 2; i++)
                    ldsm4(areg[i], sp16_u + (uint32_t)(wm + i*16 + lr)*144u + kc*16u);
                ldsm4(breg, svT_u + (uint32_t)(wn + lr)*144u + kc*16u);
                #pragma unroll
                for (int i = 0; i < 2; i++)
                    #pragma unroll
                    for (int j = 0; j < 2; j++)
                        mma16816h(O[i][j], areg[i], breg[j], breg[2 + j]);
            }
        }
    }

    #pragma unroll
    for (int i = 0; i < 2; i++) {
        int row = wm + i*16 + rr;
        float inv0 = 1.0f / lrow[row];
        float inv1 = 1.0f / lrow[row + 8];
        #pragma unroll
        for (int j = 0; j < 2; j++) {
            int col = h*64 + wn + j*8 + qq*2;
            *(float2*)(S + ((size_t)b*64 + row)*Dd + col) =
                make_float2(O[i][j][0]*inv0, O[i][j][1]*inv0);
            *(float2*)(S + ((size_t)b*64 + row + 8)*Dd + col) =
                make_float2(O[i][j][2]*inv1, O[i][j][3]*inv1);
        }
    }
}

// ===========================================================================
extern "C" void kernel_launch(void* const* d_in, const int* in_sizes, int n_in,
                              void* d_out, int out_size)
{
    (void)in_sizes; (void)out_size;
    const float* query = (const float*)d_in[0];
    const float* key   = (const float*)d_in[1];
    const float* value = (const float*)d_in[2];
    const int*   tidx  = (const int*)  d_in[3];
    const int*   sidx  = (const int*)  d_in[4];
    const float* tpm   = (const float*)d_in[5];
    const float* spm   = (const float*)d_in[6];
    const float* outb  = (const float*)d_in[n_in-1];
    const float* outw  = (const float*)d_in[n_in-2];
    const float* ipb   = (const float*)d_in[n_in-3];
    const float* ipw   = (const float*)d_in[n_in-4];
    const float* bv    = (const float*)d_in[n_in-5];
    const float* Wv    = (const float*)d_in[n_in-6];
    const float* bk    = (const float*)d_in[n_in-7];
    const float* Wk    = (const float*)d_in[n_in-8];
    const float* bq    = (const float*)d_in[n_in-9];
    const float* Wq    = (const float*)d_in[n_in-10];
    float* out = (float*)d_out;

    float *Q, *K, *V, *K2p, *V2p, *QS, *S, *Wcomb, *bck, *bcv, *zero;
    __half *Wc;
    cudaGetSymbolAddress((void**)&Q,  g_Q);
    cudaGetSymbolAddress((void**)&K,  g_K);
    cudaGetSymbolAddress((void**)&V,  g_V);
    cudaGetSymbolAddress((void**)&K2p, g_K2);
    cudaGetSymbolAddress((void**)&V2p, g_V2);
    cudaGetSymbolAddress((void**)&QS, g_QS);
    cudaGetSymbolAddress((void**)&S,  g_S);
    cudaGetSymbolAddress((void**)&Wc, g_Wc);
    cudaGetSymbolAddress((void**)&Wcomb, g_Wcomb);
    cudaGetSymbolAddress((void**)&bck, g_bck);
    cudaGetSymbolAddress((void**)&bcv, g_bcv);
    cudaGetSymbolAddress((void**)&zero, g_zero);

    cudaFuncSetAttribute(gemm_fp16,     cudaFuncAttributeMaxDynamicSharedMemorySize, GB_SMEM);
    cudaFuncSetAttribute(temporal_attn, cudaFuncAttributeMaxDynamicSharedMemorySize, TA_SMEM);
    cudaFuncSetAttribute(static_attn,   cudaFuncAttributeMaxDynamicSharedMemorySize, SA_SMEM);

    static cudaStream_t s2 = 0, s3 = 0;
    static cudaEvent_t ev0 = 0, evQx = 0, evKx = 0, evVx = 0, evQKV = 0,
                       evQS = 0, evS2 = 0, evWc = 0;
    if (!s2) {
        cudaStreamCreateWithFlags(&s2, cudaStreamNonBlocking);
        cudaStreamCreateWithFlags(&s3, cudaStreamNonBlocking);
        cudaEventCreateWithFlags(&ev0,   cudaEventDisableTiming);
        cudaEventCreateWithFlags(&evQx,  cudaEventDisableTiming);
        cudaEventCreateWithFlags(&evKx,  cudaEventDisableTiming);
        cudaEventCreateWithFlags(&evVx,  cudaEventDisableTiming);
        cudaEventCreateWithFlags(&evQKV, cudaEventDisableTiming);
        cudaEventCreateWithFlags(&evQS,  cudaEventDisableTiming);
        cudaEventCreateWithFlags(&evS2,  cudaEventDisableTiming);
        cudaEventCreateWithFlags(&evWc,  cudaEventDisableTiming);
    }

    dim3 blk(256);
    dim3 ggemm(Dd/128, Mtot/128);          // (8, 260)
    dim3 gsq(Dd/128, Dd/128);              // (8, 8)
    dim3 gsm(Dd/128, (Bb*NSs)/128);        // (8, 4)
    const int wn4 = Dd*Dd/4;
    const int wblocks = (wn4 + 255)/256;
    __half* Wc0 = Wc;
    __half* Wc1 = Wc + (size_t)1*Dd*Dd;
    __half* Wc2 = Wc + (size_t)2*Dd*Dd;
    __half* Wc3 = Wc + (size_t)3*Dd*Dd;
    __half* Wc4 = Wc + (size_t)4*Dd*Dd;
    float* Wcombk = Wcomb;
    float* Wcombv = Wcomb + (size_t)Dd*Dd;
    const float* Wk2 = ipw + (size_t)Dd*Dd;
    const float* Wv2 = ipw + (size_t)2*Dd*Dd;

    cudaEventRecord(ev0, 0);

    // ---- fork s2: weight fp16 conversions (small, fast) ----
    cudaStreamWaitEvent(s2, ev0, 0);
    conv_hi<<<wblocks, blk, 0, s2>>>(Wq, Wc0, wn4);
    cudaEventRecord(evQx, s2);
    conv_hi<<<wblocks, blk, 0, s2>>>(Wk, Wc1, wn4);
    cudaEventRecord(evKx, s2);
    conv_hi<<<wblocks, blk, 0, s2>>>(Wv, Wc2, wn4);
    cudaEventRecord(evVx, s2);

    // ---- fork s3: weight-combine chain ----
    cudaStreamWaitEvent(s3, ev0, 0);
    sgemm_bias<<<gsq, blk, 0, s3>>>(Wk2, Wk, zero, Wcombk, Dd, Dd, Dd, 0, sidx, 0, 1);
    sgemm_bias<<<gsq, blk, 0, s3>>>(Wv2, Wv, zero, Wcombv, Dd, Dd, Dd, 0, sidx, 0, 1);
    bias_comb<<<Dd, blk, 0, s3>>>(Wk2, bk, ipb + Dd,   bck);
    bias_comb<<<Dd, blk, 0, s3>>>(Wv2, bv, ipb + 2*Dd, bcv);
    conv_hi<<<wblocks, blk, 0, s3>>>(Wcombk, Wc3, wn4);
    conv_hi<<<wblocks, blk, 0, s3>>>(Wcombv, Wc4, wn4);
    cudaEventRecord(evWc, s3);

    // ---- main: Q/K/V GEMMs (fused fp32->fp16 A conversion) ----
    cudaStreamWaitEvent(0, evQx, 0);
    gemm_fp16<<<ggemm, blk, GB_SMEM>>>(query, Wc0, bq, Q);
    cudaStreamWaitEvent(0, evKx, 0);
    gemm_fp16<<<ggemm, blk, GB_SMEM>>>(key,   Wc1, bk, K);
    cudaStreamWaitEvent(0, evVx, 0);
    gemm_fp16<<<ggemm, blk, GB_SMEM>>>(value, Wc2, bv, V);
    cudaEventRecord(evQKV, 0);

    // s3: QS projection (after QKV)
    cudaStreamWaitEvent(s3, evQKV, 0);
    sgemm_bias<<<gsm, blk, 0, s3>>>(Q, ipw, ipb, QS, Bb*NSs, Dd, Dd, 1, sidx, 0, 0);
    cudaEventRecord(evQS, s3);

    // s2: temporal attention (tensor-core)
    cudaStreamWaitEvent(s2, evQKV, 0);
    temporal_attn<<<dim3(Hh, NBb, Bb), blk, TA_SMEM, s2>>>(Q, K, V, tidx, sidx, tpm, spm, out);
    cudaEventRecord(evS2, s2);

    // main: K2/V2 GEMMs (read key/value fp32 directly), static attn, out proj
    cudaStreamWaitEvent(0, evWc, 0);
    gemm_fp16<<<ggemm, blk, GB_SMEM>>>(key,   Wc3, bck, K2p);
    gemm_fp16<<<ggemm, blk, GB_SMEM>>>(value, Wc4, bcv, V2p);

    cudaStreamWaitEvent(0, evQS, 0);
    static_attn<<<dim3(Hh, Bb), blk, SA_SMEM>>>(QS, K2p, V2p, tidx, sidx, tpm, spm, S);
    sgemm_bias<<<gsm, blk>>>(S, outw, outb, out, Bb*NSs, Dd, Dd, 0, sidx, 1, 0);

    // join temporal branch back into main stream
    cudaStreamWaitEvent(0, evS2, 0);
}

// round 17
// speedup vs baseline: 1.1105x; 1.1105x over previous
#include <cuda_runtime.h>
#include <cuda_fp16.h>
#include <cstdint>
#include <cstddef>

// Problem constants
#define Bb   8
#define Ll   4160
#define Dd   1024
#define Hh   16
#define NBb  64
#define BLb  64
#define NSs  64
#define NTt  4096   // NB*BL
#define Mtot (Bb*Ll)      // 33280
#define K2c  2048         // row stride of fp16 operand buffers (only [0,1024) used)

// Scratch (device globals: allocation-free)
__device__ float g_Q [(size_t)Mtot*Dd];
__device__ float g_K [(size_t)Mtot*Dd];
__device__ float g_V [(size_t)Mtot*Dd];
__device__ float g_K2[(size_t)Mtot*Dd];
__device__ float g_V2[(size_t)Mtot*Dd];
__device__ float g_QS[(size_t)Bb*NSs*Dd];
__device__ float g_S [(size_t)Bb*NSs*Dd];
__device__ __half g_Xq[(size_t)Mtot*K2c];
__device__ __half g_Xk[(size_t)Mtot*K2c];
__device__ __half g_Xv[(size_t)Mtot*K2c];
__device__ __half g_Wc[5][(size_t)Dd*K2c];
__device__ float g_Wpart[8][(size_t)Dd*Dd];   // split-K partials (2 GEMMs x 4)
__device__ float g_bck[Dd];
__device__ float g_bcv[Dd];

// ===========================================================================
// helpers
// ===========================================================================
__device__ __forceinline__ uint32_t smem_u32(const void* p) {
    uint32_t a;
    asm("{ .reg .u64 t; cvta.to.shared.u64 t, %1; cvt.u32.u64 %0, t; }"
        : "=r"(a) : "l"(p));
    return a;
}
__device__ __forceinline__ void ldsm4(uint32_t* r, uint32_t addr) {
    asm volatile("ldmatrix.sync.aligned.m8n8.x4.shared.b16 {%0,%1,%2,%3}, [%4];"
                 : "=r"(r[0]), "=r"(r[1]), "=r"(r[2]), "=r"(r[3]) : "r"(addr));
}
__device__ __forceinline__ void mma16816h(float* d, const uint32_t* a,
                                          uint32_t b0, uint32_t b1) {
    asm volatile("mma.sync.aligned.m16n8k16.row.col.f32.f16.f16.f32 "
                 "{%0,%1,%2,%3}, {%4,%5,%6,%7}, {%8,%9}, {%0,%1,%2,%3};"
                 : "+f"(d[0]), "+f"(d[1]), "+f"(d[2]), "+f"(d[3])
                 : "r"(a[0]), "r"(a[1]), "r"(a[2]), "r"(a[3]), "r"(b0), "r"(b1));
}
__device__ __forceinline__ void cpasync16(uint32_t d, const void* g) {
    asm volatile("cp.async.cg.shared.global [%0], [%1], 16;" :: "r"(d), "l"(g));
}
__device__ __forceinline__ uint32_t packh2(__half a, __half b) {
    __half2 p = __halves2half2(a, b);
    return *(uint32_t*)&p;
}

// ===========================================================================
// Convert X fp32 [rows x 1024] -> Y fp16 hi-only (row stride K2c).
// ===========================================================================
__global__ void __launch_bounds__(256)
conv_hi(const float* __restrict__ X, __half* __restrict__ Y, int n4)
{
    int i = blockIdx.x * blockDim.x + threadIdx.x;
    if (i >= n4) return;
    float4 v = ((const float4*)X)[i];
    int e = i << 2;
    int row = e >> 10, col = e & 1023;
    uint2 hv = make_uint2(packh2(__float2half_rn(v.x), __float2half_rn(v.y)),
                          packh2(__float2half_rn(v.z), __float2half_rn(v.w)));
    *(uint2*)(Y + (size_t)row * K2c + col) = hv;
}

// ===========================================================================
// reduce 4 split-K partials -> fp16 (row stride K2c). Deterministic order.
// ===========================================================================
__global__ void __launch_bounds__(256)
reduce4h(const float* __restrict__ P, __half* __restrict__ Y, int n4)
{
    int i = blockIdx.x * blockDim.x + threadIdx.x;
    if (i >= n4) return;
    const float4* p0 = (const float4*)(P);
    const float4* p1 = (const float4*)(P + (size_t)Dd*Dd);
    const float4* p2 = (const float4*)(P + (size_t)2*Dd*Dd);
    const float4* p3 = (const float4*)(P + (size_t)3*Dd*Dd);
    float4 a = p0[i], b = p1[i], c = p2[i], d = p3[i];
    float sx = ((a.x + b.x) + c.x) + d.x;
    float sy = ((a.y + b.y) + c.y) + d.y;
    float sz = ((a.z + b.z) + c.z) + d.z;
    float sw = ((a.w + b.w) + c.w) + d.w;
    int e = i << 2;
    int row = e >> 10, col = e & 1023;
    uint2 hv = make_uint2(packh2(__float2half_rn(sx), __float2half_rn(sy)),
                          packh2(__float2half_rn(sz), __float2half_rn(sw)));
    *(uint2*)(Y + (size_t)row * K2c + col) = hv;
}

// ===========================================================================
// bias combine: out[i] = dot(W2 row i, b1) + b2[i].  grid = 1024 blocks.
// ===========================================================================
__global__ void __launch_bounds__(256)
bias_comb(const float* __restrict__ W2, const float* __restrict__ b1,
          const float* __restrict__ b2, float* __restrict__ out)
{
    __shared__ float red[256];
    int i = blockIdx.x;
    float s = 0.0f;
    for (int k = threadIdx.x; k < Dd; k += 256)
        s += W2[(size_t)i * Dd + k] * b1[k];
    red[threadIdx.x] = s;
    __syncthreads();
    for (int st = 128; st > 0; st >>= 1) {
        if (threadIdx.x < st) red[threadIdx.x] += red[threadIdx.x + st];
        __syncthreads();
    }
    if (threadIdx.x == 0) out[i] = red[0] + b2[i];
}

// ===========================================================================
// Split-K SIMT GEMM (weight combine): P[z] = A @ W over K in [z*256,(z+1)*256)
// A [1024,1024] row-major; W [1024,1024] row-major used as [K,N] (A@W).
// Grid (8, 8, 4), 128x128 tiles.
// ===========================================================================
__global__ void __launch_bounds__(256)
sgemm_splitk(const float* __restrict__ A, const float* __restrict__ W,
             float* __restrict__ P)
{
    __shared__ float As[8][128];
    __shared__ float Bs[8][128];
    const int t    = threadIdx.x;
    const int row0 = blockIdx.y * 128;
    const int col0 = blockIdx.x * 128;
    const int kb   = blockIdx.z * 256;
    const int a_r = t >> 1;
    const int a_c = (t & 1) << 2;
    const size_t a_base = (size_t)(row0 + a_r) * Dd;
    const int kk2 = t >> 5;
    const int n4  = (t & 31) << 2;
    const int tr = (t >> 4) << 3;
    const int tc = (t & 15) << 3;
    float acc[8][8];
    #pragma unroll
    for (int i = 0; i < 8; i++)
        #pragma unroll
        for (int j = 0; j < 8; j++) acc[i][j] = 0.0f;
    for (int k0 = kb; k0 < kb + 256; k0 += 8) {
        float4 av = *(const float4*)(A + a_base + k0 + a_c);
        As[a_c+0][a_r] = av.x; As[a_c+1][a_r] = av.y;
        As[a_c+2][a_r] = av.z; As[a_c+3][a_r] = av.w;
        float4 wv = *(const float4*)(W + (size_t)(k0 + kk2) * Dd + col0 + n4);
        *(float4*)&Bs[kk2][n4] = wv;
        __syncthreads();
        #pragma unroll
        for (int k = 0; k < 8; k++) {
            float ra[8], rb[8];
            *(float4*)&ra[0] = *(const float4*)&As[k][tr];
            *(float4*)&ra[4] = *(const float4*)&As[k][tr+4];
            *(float4*)&rb[0] = *(const float4*)&Bs[k][tc];
            *(float4*)&rb[4] = *(const float4*)&Bs[k][tc+4];
            #pragma unroll
            for (int i = 0; i < 8; i++)
                #pragma unroll
                for (int j = 0; j < 8; j++)
                    acc[i][j] = fmaf(ra[i], rb[j], acc[i][j]);
        }
        __syncthreads();
    }
    float* Pz = P + (size_t)blockIdx.z * Dd * Dd;
    #pragma unroll
    for (int i = 0; i < 8; i++) {
        float* cp = Pz + (size_t)(row0 + tr + i) * Dd + col0 + tc;
        #pragma unroll
        for (int j = 0; j < 8; j++) cp[j] = acc[i][j];
    }
}

// ===========================================================================
// fp16 TN GEMM (2 CTA/SM): C[M,1024] = A'[M,:1024] @ W'[1024,:1024]^T + bias
// Row strides K2c. Block 128x128, warp 32x64, k-chunk 64, 2-stage cp.async.
// ===========================================================================
#define GB_SMEM (2*32768)

__global__ void __launch_bounds__(256)
gemm_fp16(const __half* __restrict__ A, const __half* __restrict__ W,
          const float* __restrict__ bias, float* __restrict__ C)
{
    extern __shared__ char gsm[];
    const uint32_t sb = smem_u32(gsm);
    const int t = threadIdx.x;
    const int m0 = blockIdx.y * 128;
    const int n0 = blockIdx.x * 128;

    const int l = t & 31, wid = t >> 5;
    const int wm = (wid & 3) * 32;
    const int wn = (wid >> 2) * 64;
    const int lr = (l & 7) + ((l >> 3) & 1) * 8;
    const int khalf = l >> 4;

    uint32_t aoff[2], asw[2];
    #pragma unroll
    for (int i = 0; i < 2; i++) {
        int row = wm + i * 16 + lr;
        aoff[i] = row * 128;
        asw[i]  = row & 7;
    }
    uint32_t boff[4], bsw[4];
    #pragma unroll
    for (int pr = 0; pr < 4; pr++) {
        int row = wn + pr * 16 + lr;
        boff[pr] = row * 128;
        bsw[pr]  = row & 7;
    }

    float acc[2][8][4];
    #pragma unroll
    for (int i = 0; i < 2; i++)
        #pragma unroll
        for (int j = 0; j < 8; j++)
            #pragma unroll
            for (int z = 0; z < 4; z++) acc[i][j][z] = 0.0f;

    const int NCH = 16;

    auto load_chunk = [&](int s) {
        int p = s & 1;
        uint32_t sa  = sb + p * 32768;
        uint32_t sbb = sa + 16384;
        const __half* Ag = A + (size_t)m0 * K2c + s * 64;
        const __half* Wg = W + (size_t)n0 * K2c + s * 64;
        #pragma unroll
        for (int it = 0; it < 4; it++) {
            int e = it * 256 + t;
            int row = e >> 3, seg = e & 7;
            uint32_t sw = (uint32_t)((seg ^ (row & 7)) << 4);
            cpasync16(sa  + row * 128 + sw, Ag + (size_t)row * K2c + seg * 8);
            cpasync16(sbb + row * 128 + sw, Wg + (size_t)row * K2c + seg * 8);
        }
        asm volatile("cp.async.commit_group;");
    };

    load_chunk(0);

    for (int s = 0; s < NCH; s++) {
        if (s + 1 < NCH) {
            load_chunk(s + 1);
            asm volatile("cp.async.wait_group 1;");
        } else {
            asm volatile("cp.async.wait_group 0;");
        }
        __syncthreads();

        int p = s & 1;
        uint32_t sa  = sb + p * 32768;
        uint32_t sbb = sa + 16384;
        #pragma unroll
        for (int k2 = 0; k2 < 4; k2++) {
            uint32_t areg[2][4];
            #pragma unroll
            for (int i = 0; i < 2; i++)
                ldsm4(areg[i], sa + aoff[i] + ((((uint32_t)(k2*2 + khalf)) ^ asw[i]) << 4));
            uint32_t breg[4][4];
            #pragma unroll
            for (int pr = 0; pr < 4; pr++)
                ldsm4(breg[pr], sbb + boff[pr] + ((((uint32_t)(k2*2 + khalf)) ^ bsw[pr]) << 4));
            #pragma unroll
            for (int i = 0; i < 2; i++)
                #pragma unroll
                for (int j = 0; j < 8; j++)
                    mma16816h(acc[i][j], areg[i],
                              breg[j >> 1][j & 1], breg[j >> 1][2 + (j & 1)]);
        }
        __syncthreads();
    }

    const int r = l >> 2, q = l & 3;
    #pragma unroll
    for (int i = 0; i < 2; i++) {
        int row = m0 + wm + i * 16 + r;
        #pragma unroll
        for (int j = 0; j < 8; j++) {
            int col = n0 + wn + j * 8 + q * 2;
            float b0 = bias[col], b1 = bias[col + 1];
            *(float2*)(C + (size_t)row * 1024 + col) =
                make_float2(acc[i][j][0] + b0, acc[i][j][1] + b1);
            *(float2*)(C + (size_t)(row + 8) * 1024 + col) =
                make_float2(acc[i][j][2] + b0, acc[i][j][3] + b1);
        }
    }
}

// ===========================================================================
// SIMT SGEMM, 128x128 tiles: C = A @ W^T + bias
// modeA: 1 = gather rows via sidx; modeC: 1 = scatter rows to b*L+NT+q
// ===========================================================================
__global__ void __launch_bounds__(256)
sgemm_bias(const float* __restrict__ A, const float* __restrict__ W,
           const float* __restrict__ bias, float* __restrict__ C,
           int M, int N, int K,
           int modeA, const int* __restrict__ sidx, int modeC)
{
    __shared__ float As[8][128];
    __shared__ float Bs[8][128];
    const int t    = threadIdx.x;
    const int row0 = blockIdx.y * 128;
    const int col0 = blockIdx.x * 128;
    const int a_r = t >> 1;
    const int a_c = (t & 1) << 2;
    int arow = row0 + a_r;
    size_t a_base;
    if (modeA == 1) {
        int bi = arow >> 6, qq = arow & 63;
        a_base = ((size_t)bi * Ll + (size_t)sidx[qq]) * (size_t)K;
    } else {
        a_base = (size_t)arow * (size_t)K;
    }
    const size_t w_base = (size_t)(col0 + a_r) * (size_t)K;
    const int tr = (t >> 4) << 3;
    const int tc = (t & 15) << 3;
    float acc[8][8];
    #pragma unroll
    for (int i = 0; i < 8; i++)
        #pragma unroll
        for (int j = 0; j < 8; j++) acc[i][j] = 0.0f;
    for (int k0 = 0; k0 < K; k0 += 8) {
        float4 av = *(const float4*)(A + a_base + k0 + a_c);
        float4 wv = *(const float4*)(W + w_base + k0 + a_c);
        As[a_c+0][a_r] = av.x; As[a_c+1][a_r] = av.y;
        As[a_c+2][a_r] = av.z; As[a_c+3][a_r] = av.w;
        Bs[a_c+0][a_r] = wv.x; Bs[a_c+1][a_r] = wv.y;
        Bs[a_c+2][a_r] = wv.z; Bs[a_c+3][a_r] = wv.w;
        __syncthreads();
        #pragma unroll
        for (int k = 0; k < 8; k++) {
            float ra[8], rb[8];
            *(float4*)&ra[0] = *(const float4*)&As[k][tr];
            *(float4*)&ra[4] = *(const float4*)&As[k][tr+4];
            *(float4*)&rb[0] = *(const float4*)&Bs[k][tc];
            *(float4*)&rb[4] = *(const float4*)&Bs[k][tc+4];
            #pragma unroll
            for (int i = 0; i < 8; i++)
                #pragma unroll
                for (int j = 0; j < 8; j++)
                    acc[i][j] = fmaf(ra[i], rb[j], acc[i][j]);
        }
        __syncthreads();
    }
    #pragma unroll
    for (int i = 0; i < 8; i++) {
        int r = row0 + tr + i;
        int orow = (modeC == 1) ? ((r >> 6) * Ll + NTt + (r & 63)) : r;
        float* cp = C + (size_t)orow * (size_t)N + col0 + tc;
        #pragma unroll
        for (int j = 0; j < 8; j++)
            cp[j] = acc[i][j] + bias[col0 + tc + j];
    }
}

// ===========================================================================
// Temporal block attention — tensor-core version.
// ===========================================================================
#define TA_SMEM (62464 + 33792 + 512)

__global__ void __launch_bounds__(256)
temporal_attn(const float* __restrict__ Q, const float* __restrict__ K,
              const float* __restrict__ V,
              const int* __restrict__ tidx, const int* __restrict__ sidx,
              const float* __restrict__ tpm, const float* __restrict__ spm,
              float* __restrict__ out)
{
    const int h = blockIdx.x, nb = blockIdx.y, b = blockIdx.z;
    const int t = threadIdx.x;
    extern __shared__ char smc[];
    __half* sqh  = (__half*)smc;        // 64 x 72
    __half* skh  = sqh + 4608;          // 128 x 72
    __half* svT  = skh + 9216;          // 64 x 136
    __half* sp16 = svT + 8704;          // 64 x 136
    float*  sp   = (float*)(smc + 62464);
    float*  sbias= sp + 64*132;

    const uint32_t sqh_u  = smem_u32(sqh);
    const uint32_t skh_u  = smem_u32(skh);
    const uint32_t svT_u  = smem_u32(svT);
    const uint32_t sp16_u = smem_u32(sp16);

    if (t < 128) {
        float mk = (t < 64) ? tpm[((b*NBb)+nb)*BLb + t] : spm[b*NSs + (t-64)];
        sbias[t] = (mk == 1.0f) ? 0.0f : -1e30f;
    }
    for (int e = t; e < 64*64; e += 256) {
        int r = e >> 6, k = e & 63;
        int grow = tidx[nb*64 + r];
        sqh[r*72 + k] = __float2half_rn(Q[((size_t)b*Ll + grow)*Dd + h*64 + k]);
    }
    for (int e = t; e < 128*64; e += 256) {
        int r = e >> 6, k = e & 63;
        int grow = (r < 64) ? tidx[nb*64 + r] : sidx[r - 64];
        skh[r*72 + k] = __float2half_rn(K[((size_t)b*Ll + grow)*Dd + h*64 + k]);
    }
    for (int e = t; e < 128*64; e += 256) {
        int j = e >> 6, d = e & 63;
        int grow = (j < 64) ? tidx[nb*64 + j] : sidx[j - 64];
        svT[d*136 + j] = __float2half_rn(V[((size_t)b*Ll + grow)*Dd + h*64 + d]);
    }
    __syncthreads();

    const int l = t & 31, wid = t >> 5;
    const int lr = (l & 7) + ((l >> 3) & 1) * 8;
    const int khalf = l >> 4;
    const int rr = l >> 2, qq = l & 3;

    // logits = Q @ K^T * scale + bias
    {
        const int wm = (wid & 1) * 32;
        const int wn = (wid >> 1) * 32;
        float acc[2][4][4];
        #pragma unroll
        for (int i = 0; i < 2; i++)
            #pragma unroll
            for (int j = 0; j < 4; j++)
                #pragma unroll
                for (int z = 0; z < 4; z++) acc[i][j][z] = 0.0f;
        #pragma unroll
        for (int k2 = 0; k2 < 4; k2++) {
            const uint32_t kc = (uint32_t)(k2*2 + khalf);
            uint32_t areg[2][4], breg[2][4];
            #pragma unroll
            for (int i = 0; i < 2; i++)
                ldsm4(areg[i], sqh_u + (uint32_t)(wm + i*16 + lr)*144u + kc*16u);
            #pragma unroll
            for (int pr = 0; pr < 2; pr++)
                ldsm4(breg[pr], skh_u + (uint32_t)(wn + pr*16 + lr)*144u + kc*16u);
            #pragma unroll
            for (int i = 0; i < 2; i++)
                #pragma unroll
                for (int j = 0; j < 4; j++)
                    mma16816h(acc[i][j], areg[i],
                              breg[j >> 1][j & 1], breg[j >> 1][2 + (j & 1)]);
        }
        #pragma unroll
        for (int i = 0; i < 2; i++) {
            int row = wm + i*16 + rr;
            #pragma unroll
            for (int j = 0; j < 4; j++) {
                int col = wn + j*8 + qq*2;
                float b0 = sbias[col], b1 = sbias[col+1];
                sp[row*132 + col]       = acc[i][j][0]*0.125f + b0;
                sp[row*132 + col + 1]   = acc[i][j][1]*0.125f + b1;
                sp[(row+8)*132 + col]   = acc[i][j][2]*0.125f + b0;
                sp[(row+8)*132 + col+1] = acc[i][j][3]*0.125f + b1;
            }
        }
    }
    __syncthreads();

    // softmax -> fp16
    {
        const int row = t >> 2, lane4 = t & 3;
        float* rp = sp + row*132;
        __half* rp16 = sp16 + row*136;
        float mx = -1e30f;
        for (int c = lane4; c < 128; c += 4) mx = fmaxf(mx, rp[c]);
        mx = fmaxf(mx, __shfl_xor_sync(0xFFFFFFFFu, mx, 1));
        mx = fmaxf(mx, __shfl_xor_sync(0xFFFFFFFFu, mx, 2));
        float s = 0.0f;
        for (int c = lane4; c < 128; c += 4) { float p = __expf(rp[c]-mx); rp[c] = p; s += p; }
        s += __shfl_xor_sync(0xFFFFFFFFu, s, 1);
        s += __shfl_xor_sync(0xFFFFFFFFu, s, 2);
        float inv = 1.0f / s;
        for (int c = lane4; c < 128; c += 4) rp16[c] = __float2half_rn(rp[c]*inv);
    }
    __syncthreads();

    // out = P @ V
    {
        const int wm = (wid & 1) * 32;
        const int wn = (wid >> 1) * 16;
        float acc[2][2][4];
        #pragma unroll
        for (int i = 0; i < 2; i++)
            #pragma unroll
            for (int j = 0; j < 2; j++)
                #pragma unroll
                for (int z = 0; z < 4; z++) acc[i][j][z] = 0.0f;
        #pragma unroll
        for (int k2 = 0; k2 < 8; k2++) {
            const uint32_t kc = (uint32_t)(k2*2 + khalf);
            uint32_t areg[2][4], breg[4];
            #pragma unroll
            for (int i = 0; i < 2; i++)
                ldsm4(areg[i], sp16_u + (uint32_t)(wm + i*16 + lr)*272u + kc*16u);
            ldsm4(breg, svT_u + (uint32_t)(wn + lr)*272u + kc*16u);
            #pragma unroll
            for (int i = 0; i < 2; i++)
                #pragma unroll
                for (int j = 0; j < 2; j++)
                    mma16816h(acc[i][j], areg[i], breg[j], breg[2 + j]);
        }
        #pragma unroll
        for (int i = 0; i < 2; i++) {
            int row = wm + i*16 + rr;
            #pragma unroll
            for (int j = 0; j < 2; j++) {
                int col = h*64 + wn + j*8 + qq*2;
                *(float2*)(out + ((size_t)b*Ll + nb*64 + row)*Dd + col) =
                    make_float2(acc[i][j][0], acc[i][j][1]);
                *(float2*)(out + ((size_t)b*Ll + nb*64 + row + 8)*Dd + col) =
                    make_float2(acc[i][j][2], acc[i][j][3]);
            }
        }
    }
}

// ===========================================================================
// Static attention — tensor-core flash version.
// ===========================================================================
#define SA_SMEM 55296

__global__ void __launch_bounds__(256)
static_attn(const float* __restrict__ Qs, const float* __restrict__ K2,
            const float* __restrict__ V2,
            const int* __restrict__ tidx, const int* __restrict__ sidx,
            const float* __restrict__ tpm, const float* __restrict__ spm,
            float* __restrict__ S)
{
    const int h = blockIdx.x, b = blockIdx.y;
    const int t = threadIdx.x;
    extern __shared__ char smc[];
    __half* sqh  = (__half*)smc;            // 64 x 72
    __half* skh  = sqh + 4608;              // 64 x 72
    __half* svT  = skh + 4608;              // 64 x 72 (rows=d, cols=j)
    __half* sp16 = svT + 4608;              // 64 x 72
    float*  sp   = (float*)(smc + 36864);   // 64 x 68
    float*  mrow = (float*)(smc + 54272);
    float*  lrow = mrow + 64;
    float*  arow = lrow + 64;
    float*  sb2  = arow + 64;

    const uint32_t sqh_u  = smem_u32(sqh);
    const uint32_t skh_u  = smem_u32(skh);
    const uint32_t svT_u  = smem_u32(svT);
    const uint32_t sp16_u = smem_u32(sp16);

    for (int e = t; e < 4096; e += 256) {
        int r = e >> 6, k = e & 63;
        sqh[r*72 + k] = __float2half_rn(Qs[((size_t)b*64 + r)*Dd + h*64 + k]);
    }
    if (t < 64) { mrow[t] = -1e30f; lrow[t] = 0.0f; }

    const int l = t & 31, wid = t >> 5;
    const int lr = (l & 7) + ((l >> 3) & 1) * 8;
    const int khalf = l >> 4;
    const int rr = l >> 2, qq = l & 3;
    const int wm = (wid & 1) * 32;
    const int wn = (wid >> 1) * 16;

    float O[2][2][4];
    #pragma unroll
    for (int i = 0; i < 2; i++)
        #pragma unroll
        for (int j = 0; j < 2; j++)
            #pragma unroll
            for (int z = 0; z < 4; z++) O[i][j][z] = 0.0f;

    for (int jc = 0; jc < 65; jc++) {
        int base = jc * 64;
        __syncthreads();
        for (int e = t; e < 4096; e += 256) {
            int j = e >> 6, k = e & 63;
            int jj = base + j;
            int grow = (jj < NTt) ? tidx[jj] : sidx[jj - NTt];
            size_t gb = ((size_t)b*Ll + grow)*Dd + h*64 + k;
            skh[j*72 + k] = __float2half_rn(K2[gb]);
            svT[k*72 + j] = __float2half_rn(V2[gb]);
        }
        if (t < 64) {
            int jj = base + t;
            float mk = (jj < NTt) ? tpm[b*NTt + jj] : spm[b*NSs + (jj - NTt)];
            sb2[t] = (mk == 1.0f) ? 0.0f : -1e30f;
        }
        __syncthreads();

        // logits chunk: Q @ Kc^T
        {
            float acc[2][2][4];
            #pragma unroll
            for (int i = 0; i < 2; i++)
                #pragma unroll
                for (int j = 0; j < 2; j++)
                    #pragma unroll
                    for (int z = 0; z < 4; z++) acc[i][j][z] = 0.0f;
            #pragma unroll
            for (int k2 = 0; k2 < 4; k2++) {
                const uint32_t kc = (uint32_t)(k2*2 + khalf);
                uint32_t areg[2][4], breg[4];
                #pragma unroll
                for (int i = 0; i < 2; i++)
                    ldsm4(areg[i], sqh_u + (uint32_t)(wm + i*16 + lr)*144u + kc*16u);
                ldsm4(breg, skh_u + (uint32_t)(wn + lr)*144u + kc*16u);
                #pragma unroll
                for (int i = 0; i < 2; i++)
                    #pragma unroll
                    for (int j = 0; j < 2; j++)
                        mma16816h(acc[i][j], areg[i], breg[j], breg[2 + j]);
            }
            #pragma unroll
            for (int i = 0; i < 2; i++) {
                int row = wm + i*16 + rr;
                #pragma unroll
                for (int j = 0; j < 2; j++) {
                    int col = wn + j*8 + qq*2;
                    float b0 = sb2[col], b1 = sb2[col+1];
                    sp[row*68 + col]       = acc[i][j][0]*0.125f + b0;
                    sp[row*68 + col + 1]   = acc[i][j][1]*0.125f + b1;
                    sp[(row+8)*68 + col]   = acc[i][j][2]*0.125f + b0;
                    sp[(row+8)*68 + col+1] = acc[i][j][3]*0.125f + b1;
                }
            }
        }
        __syncthreads();

        // running softmax update, emit fp16 p
        {
            const int row = t >> 2, lane4 = t & 3;
            float* rp = sp + row*68;
            __half* rp16 = sp16 + row*72;
            float mold = mrow[row];
            float mx = mold;
            for (int c = lane4; c < 64; c += 4) mx = fmaxf(mx, rp[c]);
            mx = fmaxf(mx, __shfl_xor_sync(0xFFFFFFFFu, mx, 1));
            mx = fmaxf(mx, __shfl_xor_sync(0xFFFFFFFFu, mx, 2));
            float a = __expf(mold - mx);
            float ssum = 0.0f;
            for (int c = lane4; c < 64; c += 4) {
                float p = __expf(rp[c]-mx);
                rp16[c] = __float2half_rn(p);
                ssum += p;
            }
            ssum += __shfl_xor_sync(0xFFFFFFFFu, ssum, 1);
            ssum += __shfl_xor_sync(0xFFFFFFFFu, ssum, 2);
            if (lane4 == 0) {
                lrow[row] = lrow[row]*a + ssum;
                mrow[row] = mx;
                arow[row] = a;
            }
        }
        __syncthreads();

        // rescale O and accumulate P @ Vc
        {
            #pragma unroll
            for (int i = 0; i < 2; i++) {
                float a0 = arow[wm + i*16 + rr];
                float a1 = arow[wm + i*16 + rr + 8];
                #pragma unroll
                for (int j = 0; j < 2; j++) {
                    O[i][j][0] *= a0; O[i][j][1] *= a0;
                    O[i][j][2] *= a1; O[i][j][3] *= a1;
                }
            }
            #pragma unroll
            for (int k2 = 0; k2 < 4; k2++) {
                const uint32_t kc = (uint32_t)(k2*2 + khalf);
                uint32_t areg[2][4], breg[4];
                #pragma unroll
                for (int i = 0; i < 2; i++)
                    ldsm4(areg[i], sp16_u + (uint32_t)(wm + i*16 + lr)*144u + kc*16u);
                ldsm4(breg, svT_u + (uint32_t)(wn + lr)*144u + kc*16u);
                #pragma unroll
                for (int i = 0; i < 2; i++)
                    #pragma unroll
                    for (int j = 0; j < 2; j++)
                        mma16816h(O[i][j], areg[i], breg[j], breg[2 + j]);
            }
        }
    }

    #pragma unroll
    for (int i = 0; i < 2; i++) {
        int row = wm + i*16 + rr;
        float inv0 = 1.0f / lrow[row];
        float inv1 = 1.0f / lrow[row + 8];
        #pragma unroll
        for (int j = 0; j < 2; j++) {
            int col = h*64 + wn + j*8 + qq*2;
            *(float2*)(S + ((size_t)b*64 + row)*Dd + col) =
                make_float2(O[i][j][0]*inv0, O[i][j][1]*inv0);
            *(float2*)(S + ((size_t)b*64 + row + 8)*Dd + col) =
                make_float2(O[i][j][2]*inv1, O[i][j][3]*inv1);
        }
    }
}

// ===========================================================================
extern "C" void kernel_launch(void* const* d_in, const int* in_sizes, int n_in,
                              void* d_out, int out_size)
{
    (void)in_sizes; (void)out_size;
    const float* query = (const float*)d_in[0];
    const float* key   = (const float*)d_in[1];
    const float* value = (const float*)d_in[2];
    const int*   tidx  = (const int*)  d_in[3];
    const int*   sidx  = (const int*)  d_in[4];
    const float* tpm   = (const float*)d_in[5];
    const float* spm   = (const float*)d_in[6];
    const float* outb  = (const float*)d_in[n_in-1];
    const float* outw  = (const float*)d_in[n_in-2];
    const float* ipb   = (const float*)d_in[n_in-3];
    const float* ipw   = (const float*)d_in[n_in-4];
    const float* bv    = (const float*)d_in[n_in-5];
    const float* Wv    = (const float*)d_in[n_in-6];
    const float* bk    = (const float*)d_in[n_in-7];
    const float* Wk    = (const float*)d_in[n_in-8];
    const float* bq    = (const float*)d_in[n_in-9];
    const float* Wq    = (const float*)d_in[n_in-10];
    float* out = (float*)d_out;

    float *Q, *K, *V, *K2p, *V2p, *QS, *S, *Wpart, *bck, *bcv;
    __half *Xq, *Xk, *Xv, *Wc;
    cudaGetSymbolAddress((void**)&Q,  g_Q);
    cudaGetSymbolAddress((void**)&K,  g_K);
    cudaGetSymbolAddress((void**)&V,  g_V);
    cudaGetSymbolAddress((void**)&K2p, g_K2);
    cudaGetSymbolAddress((void**)&V2p, g_V2);
    cudaGetSymbolAddress((void**)&QS, g_QS);
    cudaGetSymbolAddress((void**)&S,  g_S);
    cudaGetSymbolAddress((void**)&Xq, g_Xq);
    cudaGetSymbolAddress((void**)&Xk, g_Xk);
    cudaGetSymbolAddress((void**)&Xv, g_Xv);
    cudaGetSymbolAddress((void**)&Wc, g_Wc);
    cudaGetSymbolAddress((void**)&Wpart, g_Wpart);
    cudaGetSymbolAddress((void**)&bck, g_bck);
    cudaGetSymbolAddress((void**)&bcv, g_bcv);

    cudaFuncSetAttribute(gemm_fp16,     cudaFuncAttributeMaxDynamicSharedMemorySize, GB_SMEM);
    cudaFuncSetAttribute(temporal_attn, cudaFuncAttributeMaxDynamicSharedMemorySize, TA_SMEM);
    cudaFuncSetAttribute(static_attn,   cudaFuncAttributeMaxDynamicSharedMemorySize, SA_SMEM);

    static cudaStream_t s2 = 0, s3 = 0;
    static cudaEvent_t ev0 = 0, evQx = 0, evKx = 0, evVx = 0, evQ = 0, evQKV = 0,
                       evQS = 0, evS2 = 0, evWc = 0;
    if (!s2) {
        cudaStreamCreateWithFlags(&s2, cudaStreamNonBlocking);
        cudaStreamCreateWithFlags(&s3, cudaStreamNonBlocking);
        cudaEventCreateWithFlags(&ev0,   cudaEventDisableTiming);
        cudaEventCreateWithFlags(&evQx,  cudaEventDisableTiming);
        cudaEventCreateWithFlags(&evKx,  cudaEventDisableTiming);
        cudaEventCreateWithFlags(&evVx,  cudaEventDisableTiming);
        cudaEventCreateWithFlags(&evQ,   cudaEventDisableTiming);
        cudaEventCreateWithFlags(&evQKV, cudaEventDisableTiming);
        cudaEventCreateWithFlags(&evQS,  cudaEventDisableTiming);
        cudaEventCreateWithFlags(&evS2,  cudaEventDisableTiming);
        cudaEventCreateWithFlags(&evWc,  cudaEventDisableTiming);
    }

    dim3 blk(256);
    dim3 ggemm(Dd/128, Mtot/128);          // (8, 260)
    dim3 gspk(Dd/128, Dd/128, 4);          // (8, 8, 4) split-K weight combine
    dim3 gsm(Dd/128, (Bb*NSs)/128);        // (8, 4)
    const int wn4 = Dd*Dd/4;
    const int xn4 = Mtot*Dd/4;
    const int wblocks = (wn4 + 255)/256;
    const int xblocks = (xn4 + 255)/256;
    __half* Wc0 = Wc;
    __half* Wc1 = Wc + (size_t)1*Dd*K2c;
    __half* Wc2 = Wc + (size_t)2*Dd*K2c;
    __half* Wc3 = Wc + (size_t)3*Dd*K2c;
    __half* Wc4 = Wc + (size_t)4*Dd*K2c;
    float* WpartK = Wpart;
    float* WpartV = Wpart + (size_t)4*Dd*Dd;
    const float* Wk2 = ipw + (size_t)Dd*Dd;
    const float* Wv2 = ipw + (size_t)2*Dd*Dd;

    cudaEventRecord(ev0, 0);

    // ---- fork s2: input/weight fp16 conversions ----
    cudaStreamWaitEvent(s2, ev0, 0);
    conv_hi<<<wblocks, blk, 0, s2>>>(Wq, Wc0, wn4);
    conv_hi<<<xblocks, blk, 0, s2>>>(query, Xq, xn4);
    cudaEventRecord(evQx, s2);
    conv_hi<<<wblocks, blk, 0, s2>>>(Wk, Wc1, wn4);
    conv_hi<<<xblocks, blk, 0, s2>>>(key, Xk, xn4);
    cudaEventRecord(evKx, s2);
    conv_hi<<<wblocks, blk, 0, s2>>>(Wv, Wc2, wn4);
    conv_hi<<<xblocks, blk, 0, s2>>>(value, Xv, xn4);
    cudaEventRecord(evVx, s2);

    // ---- fork s3: weight-combine (split-K x4 -> reduce to fp16) ----
    cudaStreamWaitEvent(s3, ev0, 0);
    sgemm_splitk<<<gspk, blk, 0, s3>>>(Wk2, Wk, WpartK);
    sgemm_splitk<<<gspk, blk, 0, s3>>>(Wv2, Wv, WpartV);
    reduce4h<<<wblocks, blk, 0, s3>>>(WpartK, Wc3, wn4);
    reduce4h<<<wblocks, blk, 0, s3>>>(WpartV, Wc4, wn4);
    bias_comb<<<Dd, blk, 0, s3>>>(Wk2, bk, ipb + Dd,   bck);
    bias_comb<<<Dd, blk, 0, s3>>>(Wv2, bv, ipb + 2*Dd, bcv);
    cudaEventRecord(evWc, s3);

    // ---- main: Q/K/V GEMMs ----
    cudaStreamWaitEvent(0, evQx, 0);
    gemm_fp16<<<ggemm, blk, GB_SMEM>>>(Xq, Wc0, bq, Q);
    cudaEventRecord(evQ, 0);
    cudaStreamWaitEvent(0, evKx, 0);
    gemm_fp16<<<ggemm, blk, GB_SMEM>>>(Xk, Wc1, bk, K);
    cudaStreamWaitEvent(0, evVx, 0);
    gemm_fp16<<<ggemm, blk, GB_SMEM>>>(Xv, Wc2, bv, V);
    cudaEventRecord(evQKV, 0);

    // s3: QS projection (needs only Q — starts as soon as Q is done)
    cudaStreamWaitEvent(s3, evQ, 0);
    sgemm_bias<<<gsm, blk, 0, s3>>>(Q, ipw, ipb, QS, Bb*NSs, Dd, Dd, 1, sidx, 0);
    cudaEventRecord(evQS, s3);

    // s2: temporal attention (tensor-core)
    cudaStreamWaitEvent(s2, evQKV, 0);
    temporal_attn<<<dim3(Hh, NBb, Bb), blk, TA_SMEM, s2>>>(Q, K, V, tidx, sidx, tpm, spm, out);
    cudaEventRecord(evS2, s2);

    // main: K2/V2 GEMMs, static attention, out projection
    cudaStreamWaitEvent(0, evWc, 0);
    gemm_fp16<<<ggemm, blk, GB_SMEM>>>(Xk, Wc3, bck, K2p);
    gemm_fp16<<<ggemm, blk, GB_SMEM>>>(Xv, Wc4, bcv, V2p);

    cudaStreamWaitEvent(0, evQS, 0);
    static_attn<<<dim3(Hh, Bb), blk, SA_SMEM>>>(QS, K2p, V2p, tidx, sidx, tpm, spm, S);
    sgemm_bias<<<gsm, blk>>>(S, outw, outb, out, Bb*NSs, Dd, Dd, 0, sidx, 1);

    // join temporal branch back into main stream
    cudaStreamWaitEvent(0, evS2, 0);
}